// round 3
// baseline (speedup 1.0000x reference)
#include <cuda_runtime.h>
#include <cstdint>
#include <math.h>

// Problem constants
#define B_    32
#define L_    2048
#define I_    256
#define H_    512
#define HX    768      // H + I
#define N3    1536     // 3*H (z | r | w)
#define NCG   16       // CTAs per cluster (column groups)
#define NBG   8        // clusters (batch groups)
#define BPG   4        // batches per group
#define CPG   32       // gate columns per CTA
#define NTHR  256

// ---------------- device scratch ----------------
__device__ float g_X[(size_t)L_ * B_ * N3];   // precomputed x-contributions

// ---------------- smem layout (bytes) ----------------
#define WR_OFF   0                       // Wr h-part: 32 x 512 f32
#define WZ_OFF   65536                   // Wz h-part
#define WW_OFF   131072                  // Ww h-part
#define H0_OFF   196608                  // h buffer 0: 4 x 512 f32
#define H1_OFF   204800                  // h buffer 1
#define RH_OFF   212992                  // r*h full: 4 x 512 f32
#define ZS_OFF   221184                  // z: 4 x 32 f32
#define SMEM_BYTES 221696

// ---------------- asm helpers ----------------
__device__ __forceinline__ uint32_t smem_u32(const void* p) {
    uint32_t a;
    asm("{ .reg .u64 t; cvta.to.shared.u64 t, %1; cvt.u32.u64 %0, t; }" : "=r"(a) : "l"(p));
    return a;
}
__device__ __forceinline__ unsigned long long lds64(uint32_t a) {
    unsigned long long v;
    asm volatile("ld.shared.b64 %0, [%1];" : "=l"(v) : "r"(a));
    return v;
}
__device__ __forceinline__ float lds32(uint32_t a) {
    float v;
    asm volatile("ld.shared.f32 %0, [%1];" : "=f"(v) : "r"(a));
    return v;
}
__device__ __forceinline__ void sts32(uint32_t a, float v) {
    asm volatile("st.shared.f32 [%0], %1;" :: "r"(a), "f"(v) : "memory");
}
__device__ __forceinline__ void fma2(unsigned long long& acc, unsigned long long a, unsigned long long b) {
    asm volatile("fma.rn.f32x2 %0, %1, %2, %0;" : "+l"(acc) : "l"(a), "l"(b));
}
__device__ __forceinline__ float sum2(unsigned long long v) {
    float lo, hi;
    asm("mov.b64 {%0, %1}, %2;" : "=f"(lo), "=f"(hi) : "l"(v));
    return lo + hi;
}
__device__ __forceinline__ void dsmem_st(uint32_t laddr, uint32_t rank, float v) {
    uint32_t r;
    asm volatile("mapa.shared::cluster.u32 %0, %1, %2;" : "=r"(r) : "r"(laddr), "r"(rank));
    asm volatile("st.shared::cluster.f32 [%0], %1;" :: "r"(r), "f"(v) : "memory");
}
#define CLUSTER_SYNC() do { \
    asm volatile("barrier.cluster.arrive.aligned;" ::: "memory"); \
    asm volatile("barrier.cluster.wait.aligned;"   ::: "memory"); \
} while (0)

// ---------------- precompute GEMM: g_X = x . W[:,512:768]^T ----------------
__global__ void __launch_bounds__(256) precompute_x_kernel(
    const float* __restrict__ x,
    const float* __restrict__ Wz,
    const float* __restrict__ Wr,
    const float* __restrict__ Ww)
{
    __shared__ float As[16][132];
    __shared__ float Bs[16][132];

    const int m0 = blockIdx.y * 128;
    const int n0 = blockIdx.x * 128;
    const int tid = threadIdx.x;
    const int ty = tid >> 4;
    const int tx = tid & 15;

    float acc[8][8];
#pragma unroll
    for (int i = 0; i < 8; i++)
#pragma unroll
        for (int j = 0; j < 8; j++) acc[i][j] = 0.f;

    for (int k0 = 0; k0 < 256; k0 += 16) {
#pragma unroll
        for (int q = tid; q < 512; q += 256) {
            int r  = q >> 2;
            int kq = (q & 3) << 2;
            float4 v = *(const float4*)(x + (size_t)(m0 + r) * 256 + k0 + kq);
            As[kq + 0][r] = v.x; As[kq + 1][r] = v.y;
            As[kq + 2][r] = v.z; As[kq + 3][r] = v.w;
        }
#pragma unroll
        for (int q = tid; q < 512; q += 256) {
            int r  = q >> 2;
            int kq = (q & 3) << 2;
            int n  = n0 + r;
            const float* wrow;
            if (n < 512)        wrow = Wz + (size_t)n * HX;
            else if (n < 1024)  wrow = Wr + (size_t)(n - 512) * HX;
            else                wrow = Ww + (size_t)(n - 1024) * HX;
            float4 v = *(const float4*)(wrow + 512 + k0 + kq);
            Bs[kq + 0][r] = v.x; Bs[kq + 1][r] = v.y;
            Bs[kq + 2][r] = v.z; Bs[kq + 3][r] = v.w;
        }
        __syncthreads();
#pragma unroll
        for (int kk = 0; kk < 16; kk++) {
            float a[8], b[8];
#pragma unroll
            for (int i = 0; i < 8; i++) a[i] = As[kk][ty * 8 + i];
#pragma unroll
            for (int j = 0; j < 8; j++) b[j] = Bs[kk][tx * 8 + j];
#pragma unroll
            for (int i = 0; i < 8; i++)
#pragma unroll
                for (int j = 0; j < 8; j++) acc[i][j] += a[i] * b[j];
        }
        __syncthreads();
    }

#pragma unroll
    for (int i = 0; i < 8; i++) {
        int m = m0 + ty * 8 + i;
        int t = m & 2047;
        int b = m >> 11;
        size_t base = ((size_t)t * B_ + b) * N3 + n0 + tx * 8;
        *(float4*)&g_X[base + 0] = make_float4(acc[i][0], acc[i][1], acc[i][2], acc[i][3]);
        *(float4*)&g_X[base + 4] = make_float4(acc[i][4], acc[i][5], acc[i][6], acc[i][7]);
    }
}

// ---------------- clustered recurrent kernel ----------------
__global__ void __launch_bounds__(NTHR, 1) gru_cluster_kernel(
    const float* __restrict__ h0,
    const float* __restrict__ Wz,
    const float* __restrict__ Wr,
    const float* __restrict__ Ww,
    float* __restrict__ out)
{
    extern __shared__ float sm[];
    char* smc = (char*)sm;
    const uint32_t sbase = smem_u32(sm);
    const int tid  = threadIdx.x;
    const int w    = tid >> 5;
    const int lane = tid & 31;

    uint32_t cg;
    asm("mov.u32 %0, %%cluster_ctarank;" : "=r"(cg));
    const int bg = blockIdx.y;
    const int b0 = bg * BPG;
    const int c0 = (int)cg * CPG;

    // ---- load weight h-parts: 3 x [32 rows x 512] ----
    for (int q = tid; q < 32 * 128; q += NTHR) {
        int row = q >> 7, f4 = q & 127;
        *(float4*)(smc + WR_OFF + row * 2048 + f4 * 16) = *(const float4*)(Wr + (size_t)(c0 + row) * HX + f4 * 4);
        *(float4*)(smc + WZ_OFF + row * 2048 + f4 * 16) = *(const float4*)(Wz + (size_t)(c0 + row) * HX + f4 * 4);
        *(float4*)(smc + WW_OFF + row * 2048 + f4 * 16) = *(const float4*)(Ww + (size_t)(c0 + row) * HX + f4 * 4);
    }
    // ---- load h0 for our 4 batches into buffer 0 ----
    for (int q = tid; q < 4 * 128; q += NTHR) {
        int b = q >> 7, f4 = q & 127;
        *(float4*)(smc + H0_OFF + b * 2048 + f4 * 16) = *(const float4*)(h0 + (size_t)(b0 + b) * H_ + f4 * 4);
    }
    __syncthreads();

    const int cA = lane >> 2;      // phase A col 0..3 (lane<16) / phase B col 0..7
    const int bA = lane & 3;       // batch 0..3

    for (int t = 0; t < L_; t++) {
        const uint32_t hcur = sbase + ((t & 1) ? H1_OFF : H0_OFF);
        const uint32_t hnxt = sbase + ((t & 1) ? H0_OFF : H1_OFF);
        const size_t xrow = ((size_t)t * B_ + b0 + bA) * N3;

        // ---- prefetch x-contributions (hidden behind phase A GEMM) ----
        float xv_r = 0.f, xv_b;
        if (lane < 16)
            xv_r = __ldg(&g_X[xrow + 512 + c0 + w * 4 + cA]);
        if (w < 4) xv_b = __ldg(&g_X[xrow + c0 + w * 8 + cA]);
        else       xv_b = __ldg(&g_X[xrow + 1024 + c0 + (w - 4) * 8 + cA]);

        // ================= phase A: r gates (32 cols x 4 b, k=512) =================
        {
            unsigned long long acc[4][4];
#pragma unroll
            for (int c = 0; c < 4; c++)
#pragma unroll
                for (int b = 0; b < 4; b++) acc[c][b] = 0ull;

            const uint32_t wrb = sbase + WR_OFF + (w * 4) * 2048;
#pragma unroll
            for (int i = 0; i < 8; i++) {
                uint32_t off = (uint32_t)(i * 32 + lane) * 8u;
                unsigned long long hv0 = lds64(hcur + 0 * 2048 + off);
                unsigned long long hv1 = lds64(hcur + 1 * 2048 + off);
                unsigned long long hv2 = lds64(hcur + 2 * 2048 + off);
                unsigned long long hv3 = lds64(hcur + 3 * 2048 + off);
#pragma unroll
                for (int c = 0; c < 4; c++) {
                    unsigned long long wv = lds64(wrb + c * 2048 + off);
                    fma2(acc[c][0], hv0, wv);
                    fma2(acc[c][1], hv1, wv);
                    fma2(acc[c][2], hv2, wv);
                    fma2(acc[c][3], hv3, wv);
                }
            }
            float a[16];
#pragma unroll
            for (int c = 0; c < 4; c++)
#pragma unroll
                for (int b = 0; b < 4; b++) a[c * 4 + b] = sum2(acc[c][b]);

            // 32-lane reduce of 16 chains: fold 16-halves, then sel-tree
#pragma unroll
            for (int i = 0; i < 16; i++) a[i] += __shfl_xor_sync(0xffffffffu, a[i], 16);
#pragma unroll
            for (int i = 0; i < 8; i++) {
                bool hi = (lane & 8);
                float send = hi ? a[i] : a[i + 8];
                float keep = hi ? a[i + 8] : a[i];
                a[i] = keep + __shfl_xor_sync(0xffffffffu, send, 8);
            }
#pragma unroll
            for (int i = 0; i < 4; i++) {
                bool hi = (lane & 4);
                float send = hi ? a[i] : a[i + 4];
                float keep = hi ? a[i + 4] : a[i];
                a[i] = keep + __shfl_xor_sync(0xffffffffu, send, 4);
            }
#pragma unroll
            for (int i = 0; i < 2; i++) {
                bool hi = (lane & 2);
                float send = hi ? a[i] : a[i + 2];
                float keep = hi ? a[i + 2] : a[i];
                a[i] = keep + __shfl_xor_sync(0xffffffffu, send, 2);
            }
            {
                bool hi = (lane & 1);
                float send = hi ? a[0] : a[1];
                float keep = hi ? a[1] : a[0];
                a[0] = keep + __shfl_xor_sync(0xffffffffu, send, 1);
            }

            if (lane < 16) {
                float s = a[0] + xv_r;
                float r = 1.f / (1.f + __expf(-s));
                int col = c0 + w * 4 + cA;
                float rh = r * lds32(hcur + bA * 2048 + col * 4);
                uint32_t laddr = sbase + RH_OFF + (uint32_t)(bA * 512 + col) * 4u;
#pragma unroll
                for (int p = 0; p < NCG; p++) dsmem_st(laddr, (uint32_t)p, rh);
            }
        }
        CLUSTER_SYNC();   // r*h visible cluster-wide

        // ============ phase B: z (warps 0-3, over h) + h_hat (warps 4-7, over r*h) ============
        {
            const uint32_t inb = (w < 4) ? hcur : (sbase + RH_OFF);
            const uint32_t wb  = sbase + ((w < 4) ? WZ_OFF : WW_OFF) + ((w & 3) * 8) * 2048;

            unsigned long long acc[8][4];
#pragma unroll
            for (int c = 0; c < 8; c++)
#pragma unroll
                for (int b = 0; b < 4; b++) acc[c][b] = 0ull;

#pragma unroll
            for (int i = 0; i < 8; i++) {
                uint32_t off = (uint32_t)(i * 32 + lane) * 8u;
                unsigned long long hv0 = lds64(inb + 0 * 2048 + off);
                unsigned long long hv1 = lds64(inb + 1 * 2048 + off);
                unsigned long long hv2 = lds64(inb + 2 * 2048 + off);
                unsigned long long hv3 = lds64(inb + 3 * 2048 + off);
#pragma unroll
                for (int c = 0; c < 8; c++) {
                    unsigned long long wv = lds64(wb + c * 2048 + off);
                    fma2(acc[c][0], hv0, wv);
                    fma2(acc[c][1], hv1, wv);
                    fma2(acc[c][2], hv2, wv);
                    fma2(acc[c][3], hv3, wv);
                }
            }
            float a[32];
#pragma unroll
            for (int c = 0; c < 8; c++)
#pragma unroll
                for (int b = 0; b < 4; b++) a[c * 4 + b] = sum2(acc[c][b]);

#pragma unroll
            for (int i = 0; i < 16; i++) {
                bool hi = (lane & 16);
                float send = hi ? a[i] : a[i + 16];
                float keep = hi ? a[i + 16] : a[i];
                a[i] = keep + __shfl_xor_sync(0xffffffffu, send, 16);
            }
#pragma unroll
            for (int i = 0; i < 8; i++) {
                bool hi = (lane & 8);
                float send = hi ? a[i] : a[i + 8];
                float keep = hi ? a[i + 8] : a[i];
                a[i] = keep + __shfl_xor_sync(0xffffffffu, send, 8);
            }
#pragma unroll
            for (int i = 0; i < 4; i++) {
                bool hi = (lane & 4);
                float send = hi ? a[i] : a[i + 4];
                float keep = hi ? a[i + 4] : a[i];
                a[i] = keep + __shfl_xor_sync(0xffffffffu, send, 4);
            }
#pragma unroll
            for (int i = 0; i < 2; i++) {
                bool hi = (lane & 2);
                float send = hi ? a[i] : a[i + 2];
                float keep = hi ? a[i + 2] : a[i];
                a[i] = keep + __shfl_xor_sync(0xffffffffu, send, 2);
            }
            {
                bool hi = (lane & 1);
                float send = hi ? a[0] : a[1];
                float keep = hi ? a[1] : a[0];
                a[0] = keep + __shfl_xor_sync(0xffffffffu, send, 1);
            }

            float s = a[0] + xv_b;
            const int colB = (w & 3) * 8 + cA;   // cA = lane>>2 in 0..7 here
            if (w < 4) {
                float z = 1.f / (1.f + __expf(-s));
                sts32(sbase + ZS_OFF + (uint32_t)(bA * 32 + colB) * 4u, z);
            }
            __syncthreads();
            if (w >= 4) {
                float hh = tanhf(s);
                float zv = lds32(sbase + ZS_OFF + (uint32_t)(bA * 32 + colB) * 4u);
                float hp = lds32(hcur + bA * 2048 + (c0 + colB) * 4);
                float hn = hp + zv * (hh - hp);
                out[((size_t)t * B_ + b0 + bA) * H_ + c0 + colB] = hn;
                uint32_t laddr = hnxt + (uint32_t)(bA * 2048 + (c0 + colB) * 4);
#pragma unroll
                for (int p = 0; p < NCG; p++) dsmem_st(laddr, (uint32_t)p, hn);
            }
        }
        CLUSTER_SYNC();   // h(t+1) visible cluster-wide
    }
}

// ---------------- launch ----------------
extern "C" void kernel_launch(void* const* d_in, const int* in_sizes, int n_in,
                              void* d_out, int out_size)
{
    const float* x  = (const float*)d_in[0];   // [32, 2048, 256]
    const float* h0 = (const float*)d_in[1];   // [32, 512]
    const float* Wz = (const float*)d_in[2];   // [512, 768]
    const float* Wr = (const float*)d_in[3];   // [512, 768]
    const float* Ww = (const float*)d_in[4];   // [512, 768]
    float* out = (float*)d_out;                // [2048, 32, 512]

    cudaFuncSetAttribute(gru_cluster_kernel,
                         cudaFuncAttributeMaxDynamicSharedMemorySize, SMEM_BYTES);
    cudaFuncSetAttribute(gru_cluster_kernel,
                         cudaFuncAttributeNonPortableClusterSizeAllowed, 1);

    dim3 pgrid(N3 / 128, (B_ * L_) / 128);     // (12, 512)
    precompute_x_kernel<<<pgrid, 256>>>(x, Wz, Wr, Ww);

    cudaLaunchConfig_t cfg = {};
    cfg.gridDim  = dim3(NCG, NBG, 1);          // 16 x 8 = 128 CTAs
    cfg.blockDim = dim3(NTHR, 1, 1);
    cfg.dynamicSmemBytes = SMEM_BYTES;
    cudaLaunchAttribute attrs[1];
    attrs[0].id = cudaLaunchAttributeClusterDimension;
    attrs[0].val.clusterDim.x = NCG;
    attrs[0].val.clusterDim.y = 1;
    attrs[0].val.clusterDim.z = 1;
    cfg.attrs = attrs;
    cfg.numAttrs = 1;
    cudaLaunchKernelEx(&cfg, gru_cluster_kernel, h0, Wz, Wr, Ww, out);
}

// round 4
// speedup vs baseline: 1.1821x; 1.1821x over previous
#include <cuda_runtime.h>
#include <cstdint>
#include <math.h>

typedef unsigned long long ull;

// Problem constants
#define B_    32
#define L_    2048
#define I_    256
#define H_    512
#define HX    768      // H + I
#define N3    1536     // 3*H (z | r | w)
#define NCG   16       // column groups (CTAs per batch group)
#define NBG   8        // batch groups
#define BPG   4        // batches per group
#define CPG   32       // gate columns per CTA per gate
#define NTHR  256

// ---------------- device scratch ----------------
__device__ float g_X[(size_t)L_ * B_ * N3];   // precomputed x-contributions
__device__ float g_rh[B_ * H_];               // r*h exchange
__device__ unsigned g_cnt[NBG * 32];          // per-group barrier counters
__device__ unsigned g_genv[NBG * 32];         // per-group barrier generations

// ---------------- smem layout (float offsets) ----------------
#define WR_F 0
#define WZ_F (32 * 512)
#define WW_F (64 * 512)
#define H_F  (96 * 512)        // 4 x 512
#define RH_F (H_F + 4 * 512)   // 4 x 512
#define ZS_F (RH_F + 4 * 512)  // 4 x 32
#define SM_FLOATS (ZS_F + 4 * 32)
#define SMEM_BYTES (SM_FLOATS * 4)   // 213504 B

// ---------------- asm helpers ----------------
__device__ __forceinline__ uint32_t smem_u32(const void* p) {
    uint32_t a;
    asm("{ .reg .u64 t; cvta.to.shared.u64 t, %1; cvt.u32.u64 %0, t; }" : "=r"(a) : "l"(p));
    return a;
}
__device__ __forceinline__ ull lds64(uint32_t a) {
    ull v;
    asm volatile("ld.shared.b64 %0, [%1];" : "=l"(v) : "r"(a));
    return v;
}
__device__ __forceinline__ void fma2(ull& acc, ull a, ull b) {
    asm volatile("fma.rn.f32x2 %0, %1, %2, %0;" : "+l"(acc) : "l"(a), "l"(b));
}
__device__ __forceinline__ float sum2(ull v) {
    float lo, hi;
    asm("mov.b64 {%0, %1}, %2;" : "=f"(lo), "=f"(hi) : "l"(v));
    return lo + hi;
}

// ---------------- barrier (arrive / wait split) ----------------
__device__ __forceinline__ void bar_arrive(int bg, unsigned target) {
    __threadfence();
    unsigned* cnt = &g_cnt[bg * 32];
    unsigned* gen = &g_genv[bg * 32];
    if (atomicAdd(cnt, 1u) == (unsigned)(NCG - 1)) {
        *cnt = 0u;
        __threadfence();
        atomicExch(gen, target);
    }
}
__device__ __forceinline__ void bar_wait(int bg, unsigned target) {
    unsigned* gen = &g_genv[bg * 32];
    unsigned v;
    do {
        asm volatile("ld.acquire.gpu.u32 %0, [%1];" : "=r"(v) : "l"(gen) : "memory");
    } while ((int)(v - target) < 0);
}

// ---------------- warp reduction: 16 chains over 32 lanes ----------------
// After return: thread pair (2l, 2l+1) holds chain o = (lane>>1)&15 in a[0].
__device__ __forceinline__ void reduce16(float a[16], int lane) {
#pragma unroll
    for (int o = 0; o < 8; o++) {
        bool hi = (lane & 16);
        float send = hi ? a[o] : a[o + 8];
        float keep = hi ? a[o + 8] : a[o];
        a[o] = keep + __shfl_xor_sync(0xffffffffu, send, 16);
    }
#pragma unroll
    for (int o = 0; o < 4; o++) {
        bool hi = (lane & 8);
        float send = hi ? a[o] : a[o + 4];
        float keep = hi ? a[o + 4] : a[o];
        a[o] = keep + __shfl_xor_sync(0xffffffffu, send, 8);
    }
#pragma unroll
    for (int o = 0; o < 2; o++) {
        bool hi = (lane & 4);
        float send = hi ? a[o] : a[o + 2];
        float keep = hi ? a[o + 2] : a[o];
        a[o] = keep + __shfl_xor_sync(0xffffffffu, send, 4);
    }
    {
        bool hi = (lane & 2);
        float send = hi ? a[0] : a[1];
        float keep = hi ? a[1] : a[0];
        a[0] = keep + __shfl_xor_sync(0xffffffffu, send, 2);
    }
    a[0] += __shfl_xor_sync(0xffffffffu, a[0], 1);
}

// ---------------- precompute GEMM: g_X = x . W[:,512:768]^T ----------------
__global__ void __launch_bounds__(256) precompute_x_kernel(
    const float* __restrict__ x,
    const float* __restrict__ Wz,
    const float* __restrict__ Wr,
    const float* __restrict__ Ww)
{
    __shared__ float As[16][132];
    __shared__ float Bs[16][132];

    const int m0 = blockIdx.y * 128;
    const int n0 = blockIdx.x * 128;
    const int tid = threadIdx.x;
    const int ty = tid >> 4;
    const int tx = tid & 15;

    float acc[8][8];
#pragma unroll
    for (int i = 0; i < 8; i++)
#pragma unroll
        for (int j = 0; j < 8; j++) acc[i][j] = 0.f;

    for (int k0 = 0; k0 < 256; k0 += 16) {
#pragma unroll
        for (int q = tid; q < 512; q += 256) {
            int r  = q >> 2;
            int kq = (q & 3) << 2;
            float4 v = *(const float4*)(x + (size_t)(m0 + r) * 256 + k0 + kq);
            As[kq + 0][r] = v.x; As[kq + 1][r] = v.y;
            As[kq + 2][r] = v.z; As[kq + 3][r] = v.w;
        }
#pragma unroll
        for (int q = tid; q < 512; q += 256) {
            int r  = q >> 2;
            int kq = (q & 3) << 2;
            int n  = n0 + r;
            const float* wrow;
            if (n < 512)        wrow = Wz + (size_t)n * HX;
            else if (n < 1024)  wrow = Wr + (size_t)(n - 512) * HX;
            else                wrow = Ww + (size_t)(n - 1024) * HX;
            float4 v = *(const float4*)(wrow + 512 + k0 + kq);
            Bs[kq + 0][r] = v.x; Bs[kq + 1][r] = v.y;
            Bs[kq + 2][r] = v.z; Bs[kq + 3][r] = v.w;
        }
        __syncthreads();
#pragma unroll
        for (int kk = 0; kk < 16; kk++) {
            float a[8], b[8];
#pragma unroll
            for (int i = 0; i < 8; i++) a[i] = As[kk][ty * 8 + i];
#pragma unroll
            for (int j = 0; j < 8; j++) b[j] = Bs[kk][tx * 8 + j];
#pragma unroll
            for (int i = 0; i < 8; i++)
#pragma unroll
                for (int j = 0; j < 8; j++) acc[i][j] += a[i] * b[j];
        }
        __syncthreads();
    }

#pragma unroll
    for (int i = 0; i < 8; i++) {
        int m = m0 + ty * 8 + i;
        int t = m & 2047;
        int b = m >> 11;
        size_t base = ((size_t)t * B_ + b) * N3 + n0 + tx * 8;
        *(float4*)&g_X[base + 0] = make_float4(acc[i][0], acc[i][1], acc[i][2], acc[i][3]);
        *(float4*)&g_X[base + 4] = make_float4(acc[i][4], acc[i][5], acc[i][6], acc[i][7]);
    }
}

// ---------------- persistent recurrent kernel ----------------
__global__ void __launch_bounds__(NTHR, 1) gru_persistent_kernel(
    const float* __restrict__ h0,
    const float* __restrict__ Wz,
    const float* __restrict__ Wr,
    const float* __restrict__ Ww,
    float* __restrict__ out)
{
    extern __shared__ float sm[];
    const uint32_t sb = smem_u32(sm);
    const int tid  = threadIdx.x;
    const int wg   = tid >> 5;
    const int lane = tid & 31;
    const int cta  = blockIdx.x;
    const int cg   = cta & (NCG - 1);
    const int bg   = cta >> 4;
    const int b0   = bg * BPG;
    const int c0   = cg * CPG;

    // ---- cache weight h-parts: 3 x [32 rows x 512] ----
    for (int q = tid; q < 32 * 128; q += NTHR) {
        int row = q >> 7, f4 = q & 127;
        ((float4*)(sm + WR_F))[row * 128 + f4] = *(const float4*)(Wr + (size_t)(c0 + row) * HX + f4 * 4);
        ((float4*)(sm + WZ_F))[row * 128 + f4] = *(const float4*)(Wz + (size_t)(c0 + row) * HX + f4 * 4);
        ((float4*)(sm + WW_F))[row * 128 + f4] = *(const float4*)(Ww + (size_t)(c0 + row) * HX + f4 * 4);
    }
    __syncthreads();

    unsigned gen0;
    asm volatile("ld.acquire.gpu.u32 %0, [%1];" : "=r"(gen0) : "l"(&g_genv[bg * 32]) : "memory");

    // output mapping: even lanes own output o = (lane>>1)&15 = c*4+b
    const int o   = (lane >> 1) & 15;
    const int oc  = o >> 2;              // col within warp's 4
    const int ob  = o & 3;               // batch within group
    const int colg = c0 + wg * 4 + oc;   // global gate column (0..511)
    const int coll = wg * 4 + oc;        // local column (0..31)
    const bool wr = !(lane & 1);

    for (int t = 0; t < L_; t++) {
        const float* hsrc = (t == 0) ? h0 : (out + (size_t)(t - 1) * B_ * H_);

        // ---- stage h(t) for our 4 batches ----
        for (int q = tid; q < 512; q += NTHR) {
            int b = q >> 7, f4 = q & 127;
            float4 v = __ldcg(((const float4*)(hsrc + (size_t)(b0 + b) * H_)) + f4);
            *(float4*)(sm + H_F + b * 512 + f4 * 4) = v;
        }
        __syncthreads();

        // ---- load h slice into registers (reused by r and z gates) ----
        ull hb[4][8];
#pragma unroll
        for (int b = 0; b < 4; b++)
#pragma unroll
            for (int i = 0; i < 8; i++)
                hb[b][i] = lds64(sb + (H_F + b * 512) * 4 + (i * 32 + lane) * 8);

        const size_t xbase = ((size_t)t * B_ + b0 + ob) * N3;

        // ================= r gate =================
        {
            float xr = __ldg(&g_X[xbase + 512 + colg]);
            ull acc[4][4];
#pragma unroll
            for (int c = 0; c < 4; c++)
#pragma unroll
                for (int b = 0; b < 4; b++) acc[c][b] = 0ull;

            const uint32_t wb = sb + (WR_F + (wg * 4) * 512) * 4;
#pragma unroll
            for (int i = 0; i < 8; i++) {
                uint32_t off = (uint32_t)(i * 32 + lane) * 8u;
#pragma unroll
                for (int c = 0; c < 4; c++) {
                    ull wv = lds64(wb + c * 2048 + off);
                    fma2(acc[c][0], hb[0][i], wv);
                    fma2(acc[c][1], hb[1][i], wv);
                    fma2(acc[c][2], hb[2][i], wv);
                    fma2(acc[c][3], hb[3][i], wv);
                }
            }
            float a[16];
#pragma unroll
            for (int c = 0; c < 4; c++)
#pragma unroll
                for (int b = 0; b < 4; b++) a[c * 4 + b] = sum2(acc[c][b]);
            reduce16(a, lane);

            if (wr) {
                float s = a[0] + xr;
                float r = 1.f / (1.f + __expf(-s));
                float rh = r * sm[H_F + ob * 512 + colg];
                __stcg(&g_rh[(size_t)(b0 + ob) * H_ + colg], rh);
            }
        }
        __syncthreads();
        if (tid == 0) bar_arrive(bg, gen0 + (unsigned)(2 * t + 1));

        // ================= z gate (overlaps barrier A propagation) =================
        {
            float xz = __ldg(&g_X[xbase + colg]);
            ull acc[4][4];
#pragma unroll
            for (int c = 0; c < 4; c++)
#pragma unroll
                for (int b = 0; b < 4; b++) acc[c][b] = 0ull;

            const uint32_t wb = sb + (WZ_F + (wg * 4) * 512) * 4;
#pragma unroll
            for (int i = 0; i < 8; i++) {
                uint32_t off = (uint32_t)(i * 32 + lane) * 8u;
#pragma unroll
                for (int c = 0; c < 4; c++) {
                    ull wv = lds64(wb + c * 2048 + off);
                    fma2(acc[c][0], hb[0][i], wv);
                    fma2(acc[c][1], hb[1][i], wv);
                    fma2(acc[c][2], hb[2][i], wv);
                    fma2(acc[c][3], hb[3][i], wv);
                }
            }
            float a[16];
#pragma unroll
            for (int c = 0; c < 4; c++)
#pragma unroll
                for (int b = 0; b < 4; b++) a[c * 4 + b] = sum2(acc[c][b]);
            reduce16(a, lane);

            if (wr) {
                float z = 1.f / (1.f + __expf(-(a[0] + xz)));
                sm[ZS_F + ob * 32 + coll] = z;
            }
        }

        // ---- wait for all r*h in group, then stage it ----
        bar_wait(bg, gen0 + (unsigned)(2 * t + 1));
        for (int q = tid; q < 512; q += NTHR) {
            int b = q >> 7, f4 = q & 127;
            float4 v = __ldcg(((const float4*)(g_rh + (size_t)(b0 + b) * H_)) + f4);
            *(float4*)(sm + RH_F + b * 512 + f4 * 4) = v;
        }
        __syncthreads();

        // ================= w gate (candidate) + blend =================
        {
            float xw = __ldg(&g_X[xbase + 1024 + colg]);
            ull rb[4][8];
#pragma unroll
            for (int b = 0; b < 4; b++)
#pragma unroll
                for (int i = 0; i < 8; i++)
                    rb[b][i] = lds64(sb + (RH_F + b * 512) * 4 + (i * 32 + lane) * 8);

            ull acc[4][4];
#pragma unroll
            for (int c = 0; c < 4; c++)
#pragma unroll
                for (int b = 0; b < 4; b++) acc[c][b] = 0ull;

            const uint32_t wb = sb + (WW_F + (wg * 4) * 512) * 4;
#pragma unroll
            for (int i = 0; i < 8; i++) {
                uint32_t off = (uint32_t)(i * 32 + lane) * 8u;
#pragma unroll
                for (int c = 0; c < 4; c++) {
                    ull wv = lds64(wb + c * 2048 + off);
                    fma2(acc[c][0], rb[0][i], wv);
                    fma2(acc[c][1], rb[1][i], wv);
                    fma2(acc[c][2], rb[2][i], wv);
                    fma2(acc[c][3], rb[3][i], wv);
                }
            }
            float a[16];
#pragma unroll
            for (int c = 0; c < 4; c++)
#pragma unroll
                for (int b = 0; b < 4; b++) a[c * 4 + b] = sum2(acc[c][b]);
            reduce16(a, lane);

            if (wr) {
                float hh = tanhf(a[0] + xw);
                float zv = sm[ZS_F + ob * 32 + coll];
                float hp = sm[H_F + ob * 512 + colg];
                float hn = hp + zv * (hh - hp);
                __stcg(&out[((size_t)t * B_ + b0 + ob) * H_ + colg], hn);
            }
        }
        __syncthreads();
        if (tid == 0) bar_arrive(bg, gen0 + (unsigned)(2 * t + 2));
        bar_wait(bg, gen0 + (unsigned)(2 * t + 2));
    }
}

// ---------------- launch ----------------
extern "C" void kernel_launch(void* const* d_in, const int* in_sizes, int n_in,
                              void* d_out, int out_size)
{
    const float* x  = (const float*)d_in[0];   // [32, 2048, 256]
    const float* h0 = (const float*)d_in[1];   // [32, 512]
    const float* Wz = (const float*)d_in[2];   // [512, 768]
    const float* Wr = (const float*)d_in[3];   // [512, 768]
    const float* Ww = (const float*)d_in[4];   // [512, 768]
    float* out = (float*)d_out;                // [2048, 32, 512]

    cudaFuncSetAttribute(gru_persistent_kernel,
                         cudaFuncAttributeMaxDynamicSharedMemorySize, SMEM_BYTES);

    dim3 pgrid(N3 / 128, (B_ * L_) / 128);     // (12, 512)
    precompute_x_kernel<<<pgrid, 256>>>(x, Wz, Wr, Ww);

    gru_persistent_kernel<<<NCG * NBG, NTHR, SMEM_BYTES>>>(h0, Wz, Wr, Ww, out);
}